// round 7
// baseline (speedup 1.0000x reference)
#include <cuda_runtime.h>
#include <cuda_bf16.h>
#include <stdint.h>

#define NMAX   100000
#define F      128
#define DCAP   64          // bucket capacity per node (P(deg>64) ~ 0 for lambda=6.4)
#define OVFMAX 8192        // overflow-edge safety list

// Scratch (allocation-free rule: __device__ globals)
__device__ float g_xw[NMAX * F];
__device__ float g_hw[NMAX * F];
__device__ int   g_cursor[NMAX + 1];      // [N] = overflow counter
__device__ int   g_eidx[NMAX * DCAP];     // per-dst neighbor buckets
__device__ int   g_ovf [2 * OVFMAX];      // (r,c) pairs that overflowed
// W in mma B-fragment layout: [layer][hl][ktile(8)][warp_n(4)][lane(32)][8 u32]
__device__ uint32_t g_wfrag[2][2][8][4][32][8];

// ---------------------------------------------------------------------------
// Helpers
// ---------------------------------------------------------------------------
__device__ __forceinline__ uint32_t smem_u32(const void* p) {
    uint32_t a;
    asm("{ .reg .u64 t; cvta.to.shared.u64 t, %1; cvt.u32.u64 %0, t; }" : "=r"(a) : "l"(p));
    return a;
}
__device__ __forceinline__ uint32_t pack_hi(float a, float b) {
    __nv_bfloat16 x = __float2bfloat16_rn(a), y = __float2bfloat16_rn(b);
    return (uint32_t)*(unsigned short*)&x | ((uint32_t)*(unsigned short*)&y << 16);
}
__device__ __forceinline__ uint32_t pack_lo(float a, float b) {
    __nv_bfloat16 x = __float2bfloat16_rn(a), y = __float2bfloat16_rn(b);
    float ra = a - __bfloat162float(x), rb = b - __bfloat162float(y);
    __nv_bfloat16 lx = __float2bfloat16_rn(ra), ly = __float2bfloat16_rn(rb);
    return (uint32_t)*(unsigned short*)&lx | ((uint32_t)*(unsigned short*)&ly << 16);
}
__device__ __forceinline__ void mma_bf16(float* d, const uint32_t* a, uint32_t b0, uint32_t b1) {
    asm volatile(
        "mma.sync.aligned.m16n8k16.row.col.f32.bf16.bf16.f32 "
        "{%0,%1,%2,%3}, {%4,%5,%6,%7}, {%8,%9}, {%0,%1,%2,%3};"
        : "+f"(d[0]), "+f"(d[1]), "+f"(d[2]), "+f"(d[3])
        : "r"(a[0]), "r"(a[1]), "r"(a[2]), "r"(a[3]), "r"(b0), "r"(b1));
}
__device__ __forceinline__ void ldsm4(uint32_t* r, uint32_t addr) {
    asm volatile("ldmatrix.sync.aligned.m8n8.x4.shared.b16 {%0,%1,%2,%3}, [%4];"
                 : "=r"(r[0]), "=r"(r[1]), "=r"(r[2]), "=r"(r[3]) : "r"(addr));
}

// Warp-cooperative gather-aggregate for one destination node.
// Returns this lane's float4 (cols [4*lane, 4*lane+4)) of:
//   bias + dinv[c]^2*src[c] + sum_{r in in(c)} dinv[c]*dinv[r]*src[r]
__device__ __forceinline__ float4 gather_node(
    const float* __restrict__ src, const float* __restrict__ bias,
    int node, int lane)
{
    int cr = __ldg(&g_cursor[node]);
    float dc = rsqrtf((float)(cr + 1));
    float s  = dc * dc;

    float4 acc = __ldg((const float4*)(src + (size_t)node * F) + lane);
    float4 bb  = __ldg((const float4*)bias + lane);
    acc.x = fmaf(acc.x, s, bb.x);
    acc.y = fmaf(acc.y, s, bb.y);
    acc.z = fmaf(acc.z, s, bb.z);
    acc.w = fmaf(acc.w, s, bb.w);

    int cnt = min(cr, DCAP);
    const int* bucket = g_eidx + (size_t)node * DCAP;

    for (int base = 0; base < cnt; base += 32) {
        int id = 0;
        if (base + lane < cnt) id = __ldg(bucket + base + lane);
        int m = min(cnt - base, 32);
        #pragma unroll 4
        for (int j = 0; j < m; j++) {
            int r = __shfl_sync(0xffffffff, id, j);
            float dr = rsqrtf((float)(__ldg(&g_cursor[r]) + 1));
            float w = dc * dr;
            float4 v = __ldg((const float4*)(src + (size_t)r * F) + lane);
            acc.x = fmaf(v.x, w, acc.x);
            acc.y = fmaf(v.y, w, acc.y);
            acc.z = fmaf(v.z, w, acc.z);
            acc.w = fmaf(v.w, w, acc.w);
        }
    }

    // Overflow slow path (empty in practice; correctness insurance)
    if (cr > DCAP) {
        int ovfn = min(__ldg(&g_cursor[NMAX]), OVFMAX);
        for (int e = 0; e < ovfn; e++) {
            if (g_ovf[2 * e + 1] == node) {
                int r = g_ovf[2 * e];
                float dr = rsqrtf((float)(__ldg(&g_cursor[r]) + 1));
                float w = dc * dr;
                float4 v = __ldg((const float4*)(src + (size_t)r * F) + lane);
                acc.x = fmaf(v.x, w, acc.x);
                acc.y = fmaf(v.y, w, acc.y);
                acc.z = fmaf(v.z, w, acc.z);
                acc.w = fmaf(v.w, w, acc.w);
            }
        }
    }
    return acc;
}

// ---------------------------------------------------------------------------
// W split into mma B-fragment layout (hi/lo bf16) — both layers, one launch.
// ---------------------------------------------------------------------------
__global__ void k_wsplit(const float* __restrict__ W1, const float* __restrict__ W2) {
    int id = blockIdx.x * blockDim.x + threadIdx.x;   // 32768 total
    if (id >= 2 * 16384) return;
    int layer = id >> 14;
    int v     = id & 16383;
    int jr   = v & 7;
    int lane = (v >> 3) & 31;
    int wn   = (v >> 8) & 3;
    int kt   = (v >> 10) & 7;
    int hl   = v >> 13;
    int j = jr >> 1, r = jr & 1;
    int n = (wn * 4 + j) * 8 + (lane >> 2);
    int k = kt * 16 + (lane & 3) * 2 + r * 8;
    const float* W = layer ? W2 : W1;
    float v0 = W[k * F + n];
    float v1 = W[(k + 1) * F + n];
    g_wfrag[layer][hl][kt][wn][lane][jr] = (hl == 0) ? pack_hi(v0, v1) : pack_lo(v0, v1);
}

// ---------------------------------------------------------------------------
// GEMM MMA mainloop + epilogue (after Ah/Al smem is filled)
// ---------------------------------------------------------------------------
__device__ __forceinline__ void gemm_main(
    __nv_bfloat16 (*Ah)[136], __nv_bfloat16 (*Al)[136],
    const uint32_t* __restrict__ wfrag, float* __restrict__ outP,
    int M, int block_row, int wid, int lane)
{
    const int wm = wid >> 2;
    const int wn = wid & 3;

    float acc[2][4][4];
    #pragma unroll
    for (int mt = 0; mt < 2; mt++)
        #pragma unroll
        for (int j = 0; j < 4; j++)
            #pragma unroll
            for (int q = 0; q < 4; q++) acc[mt][j][q] = 0.f;

    const int mat = lane >> 3, rr = lane & 7;
    const int lrow  = (mat & 1) * 8 + rr;
    const int lkoff = (mat >> 1) * 8;
    const uint32_t aBaseH = smem_u32(&Ah[0][0]);
    const uint32_t aBaseL = smem_u32(&Al[0][0]);

    #pragma unroll
    for (int ks = 0; ks < 8; ks++) {
        uint32_t ah[2][4], al[2][4];
        #pragma unroll
        for (int mt = 0; mt < 2; mt++) {
            uint32_t off = (uint32_t)(((wm * 32 + mt * 16 + lrow) * 136 + ks * 16 + lkoff) * 2);
            ldsm4(ah[mt], aBaseH + off);
            ldsm4(al[mt], aBaseL + off);
        }
        const uint32_t* p_h = wfrag + (((size_t)(0 * 8 + ks) * 4 + wn) * 32 + lane) * 8;
        const uint32_t* p_l = wfrag + (((size_t)(1 * 8 + ks) * 4 + wn) * 32 + lane) * 8;
        uint4 h0 = *(const uint4*)p_h, h1 = *(const uint4*)(p_h + 4);
        uint4 l0 = *(const uint4*)p_l, l1 = *(const uint4*)(p_l + 4);
        uint32_t bh[8] = {h0.x,h0.y,h0.z,h0.w,h1.x,h1.y,h1.z,h1.w};
        uint32_t bl[8] = {l0.x,l0.y,l0.z,l0.w,l1.x,l1.y,l1.z,l1.w};

        #pragma unroll
        for (int mt = 0; mt < 2; mt++)
            #pragma unroll
            for (int j = 0; j < 4; j++) {
                mma_bf16(acc[mt][j], ah[mt], bh[2*j], bh[2*j+1]);
                mma_bf16(acc[mt][j], ah[mt], bl[2*j], bl[2*j+1]);
                mma_bf16(acc[mt][j], al[mt], bh[2*j], bh[2*j+1]);
            }
    }

    const int qrow = lane >> 2;
    const int qcol = (lane & 3) * 2;
    #pragma unroll
    for (int mt = 0; mt < 2; mt++) {
        int r0 = block_row + wm * 32 + mt * 16 + qrow;
        int r1 = r0 + 8;
        #pragma unroll
        for (int j = 0; j < 4; j++) {
            int c = wn * 32 + j * 8 + qcol;
            if (r0 < M) *(float2*)(outP + (size_t)r0 * F + c) = make_float2(acc[mt][j][0], acc[mt][j][1]);
            if (r1 < M) *(float2*)(outP + (size_t)r1 * F + c) = make_float2(acc[mt][j][2], acc[mt][j][3]);
        }
    }
}

// ---------------------------------------------------------------------------
// Mega kernel 1: GEMM layer-1 blocks (A read dense) + edge-scatter blocks
// ---------------------------------------------------------------------------
__global__ void __launch_bounds__(256, 2)
k_mega1(const float* __restrict__ A, const uint32_t* __restrict__ wfrag,
        float* __restrict__ outP, const int* __restrict__ ei,
        int M, int E, int gemm_blocks)
{
    if ((int)blockIdx.x < gemm_blocks) {
        __shared__ __align__(16) __nv_bfloat16 Ah[64][136];
        __shared__ __align__(16) __nv_bfloat16 Al[64][136];
        const int tid = threadIdx.x;
        const int block_row = blockIdx.x * 64;
        #pragma unroll
        for (int it = 0; it < 4; it++) {
            int seg = it * 256 + tid;
            int r  = seg >> 4;
            int sk = (seg & 15) * 8;
            int grow = block_row + r;
            float4 a0 = make_float4(0.f,0.f,0.f,0.f), a1 = a0;
            if (grow < M) {
                a0 = *(const float4*)(A + (size_t)grow * F + sk);
                a1 = *(const float4*)(A + (size_t)grow * F + sk + 4);
            }
            *(uint4*)&Ah[r][sk] = make_uint4(pack_hi(a0.x,a0.y), pack_hi(a0.z,a0.w),
                                             pack_hi(a1.x,a1.y), pack_hi(a1.z,a1.w));
            *(uint4*)&Al[r][sk] = make_uint4(pack_lo(a0.x,a0.y), pack_lo(a0.z,a0.w),
                                             pack_lo(a1.x,a1.y), pack_lo(a1.z,a1.w));
        }
        __syncthreads();
        gemm_main(Ah, Al, wfrag, outP, M, block_row, tid >> 5, tid & 31);
        return;
    }
    // scatter: bucket edges by destination
    int e = (blockIdx.x - gemm_blocks) * 256 + threadIdx.x;
    if (e < E) {
        int r = __ldg(ei + e);
        int c = __ldg(ei + E + e);
        int pos = atomicAdd(&g_cursor[c], 1);
        if (pos < DCAP) {
            g_eidx[(size_t)c * DCAP + pos] = r;
        } else {
            int o = atomicAdd(&g_cursor[NMAX], 1);
            if (o < OVFMAX) { g_ovf[2 * o] = r; g_ovf[2 * o + 1] = c; }
        }
    }
}

// ---------------------------------------------------------------------------
// Fused kernel: A-tile = relu(agg(src) + bias) built by warp-gather, then GEMM.
//   outP = relu(Â·src + b) @ W2
// ---------------------------------------------------------------------------
__global__ void __launch_bounds__(256, 2)
k_agg_gemm(const float* __restrict__ src, const float* __restrict__ bias,
           const uint32_t* __restrict__ wfrag, float* __restrict__ outP, int M)
{
    __shared__ __align__(16) __nv_bfloat16 Ah[64][136];
    __shared__ __align__(16) __nv_bfloat16 Al[64][136];

    const int tid  = threadIdx.x;
    const int wid  = tid >> 5;
    const int lane = tid & 31;
    const int block_row = blockIdx.x * 64;

    // Stage 1: each warp gather-aggregates 8 rows, relu, split to bf16 hi/lo.
    #pragma unroll 1
    for (int i = 0; i < 8; i++) {
        int r = wid * 8 + i;
        int node = block_row + r;
        float4 acc = make_float4(0.f, 0.f, 0.f, 0.f);
        if (node < M) {
            acc = gather_node(src, bias, node, lane);
            acc.x = fmaxf(acc.x, 0.f); acc.y = fmaxf(acc.y, 0.f);
            acc.z = fmaxf(acc.z, 0.f); acc.w = fmaxf(acc.w, 0.f);
        }
        *(uint2*)&Ah[r][lane * 4] = make_uint2(pack_hi(acc.x, acc.y), pack_hi(acc.z, acc.w));
        *(uint2*)&Al[r][lane * 4] = make_uint2(pack_lo(acc.x, acc.y), pack_lo(acc.z, acc.w));
    }
    __syncthreads();

    // Stage 2: MMA mainloop + epilogue
    gemm_main(Ah, Al, wfrag, outP, M, block_row, wid, lane);
}

// ---------------------------------------------------------------------------
// Final aggregation: one warp per destination node (no relu), writes out.
// ---------------------------------------------------------------------------
__global__ void __launch_bounds__(256)
k_agg(const float* __restrict__ src, const float* __restrict__ bias,
      float* __restrict__ dst, int N)
{
    int node = blockIdx.x * (blockDim.x >> 5) + (threadIdx.x >> 5);
    if (node >= N) return;
    int lane = threadIdx.x & 31;
    float4 acc = gather_node(src, bias, node, lane);
    *((float4*)(dst + (size_t)node * F) + lane) = acc;
}

// ---------------------------------------------------------------------------
// Launch
// ---------------------------------------------------------------------------
extern "C" void kernel_launch(void* const* d_in, const int* in_sizes, int n_in,
                              void* d_out, int out_size)
{
    const float* x  = (const float*)d_in[0];
    const int*   ei = (const int*)d_in[1];
    const float* W1 = (const float*)d_in[2];
    const float* b1 = (const float*)d_in[3];
    const float* W2 = (const float*)d_in[4];
    const float* b2 = (const float*)d_in[5];
    float*       out = (float*)d_out;

    const int N = in_sizes[0] / F;   // 100000
    const int E = in_sizes[1] / 2;   // 640000

    float* xw;   cudaGetSymbolAddress((void**)&xw, g_xw);
    float* hw;   cudaGetSymbolAddress((void**)&hw, g_hw);
    int* cursor; cudaGetSymbolAddress((void**)&cursor, g_cursor);
    uint32_t* wfrag; cudaGetSymbolAddress((void**)&wfrag, g_wfrag);
    const size_t WFRAG_LAYER = 2ull * 8 * 4 * 32 * 8;

    const int gemm_blocks = (N + 63) / 64;
    const int scat_blocks = (E + 255) / 256;
    const int agg_blocks  = (N + 7) / 8;

    // Zero bucket cursors + overflow counter
    cudaMemsetAsync(cursor, 0, (NMAX + 1) * sizeof(int));

    // W pre-split (both layers, one launch)
    k_wsplit<<<128, 256>>>(W1, W2);

    // GEMM1 + edge scatter fused
    k_mega1<<<gemm_blocks + scat_blocks, 256>>>(x, wfrag, xw, ei, N, E, gemm_blocks);

    // Fused: hw = relu(Â·xw + b1) @ W2
    k_agg_gemm<<<gemm_blocks, 256>>>(xw, b1, wfrag + WFRAG_LAYER, hw, N);

    // Final: out = Â·hw + b2
    k_agg<<<agg_blocks, 256>>>(hw, b2, out, N);
}

// round 8
// speedup vs baseline: 1.1873x; 1.1873x over previous
#include <cuda_runtime.h>
#include <cuda_bf16.h>
#include <stdint.h>

#define NMAX   100000
#define F      128
#define DCAP   64          // bucket capacity per node (P(deg>64) ~ 0 for lambda=6.4)
#define OVFMAX 8192        // overflow-edge safety list

// Scratch (allocation-free rule: __device__ globals)
__device__ float g_xw  [NMAX * F];
__device__ float g_acc1[NMAX * F];
__device__ float g_hw  [NMAX * F];
__device__ int   g_cursor[NMAX + 1];      // [N] = overflow counter
__device__ int   g_eidx[NMAX * DCAP];     // per-dst neighbor buckets
__device__ float g_ew  [NMAX * DCAP];     // per-slot edge weight dinv[c]*dinv[r]
__device__ float g_dinvf[NMAX];
__device__ int   g_ovf [2 * OVFMAX];      // (r,c) pairs that overflowed
// W in mma B-fragment layout: [layer][hl][ktile(8)][warp_n(4)][lane(32)][8 u32]
__device__ uint32_t g_wfrag[2][2][8][4][32][8];

// ---------------------------------------------------------------------------
// Helpers
// ---------------------------------------------------------------------------
__device__ __forceinline__ uint32_t smem_u32(const void* p) {
    uint32_t a;
    asm("{ .reg .u64 t; cvta.to.shared.u64 t, %1; cvt.u32.u64 %0, t; }" : "=r"(a) : "l"(p));
    return a;
}
__device__ __forceinline__ uint32_t pack_hi(float a, float b) {
    __nv_bfloat16 x = __float2bfloat16_rn(a), y = __float2bfloat16_rn(b);
    return (uint32_t)*(unsigned short*)&x | ((uint32_t)*(unsigned short*)&y << 16);
}
__device__ __forceinline__ uint32_t pack_lo(float a, float b) {
    __nv_bfloat16 x = __float2bfloat16_rn(a), y = __float2bfloat16_rn(b);
    float ra = a - __bfloat162float(x), rb = b - __bfloat162float(y);
    __nv_bfloat16 lx = __float2bfloat16_rn(ra), ly = __float2bfloat16_rn(rb);
    return (uint32_t)*(unsigned short*)&lx | ((uint32_t)*(unsigned short*)&ly << 16);
}
__device__ __forceinline__ void mma_bf16(float* d, const uint32_t* a, uint32_t b0, uint32_t b1) {
    asm volatile(
        "mma.sync.aligned.m16n8k16.row.col.f32.bf16.bf16.f32 "
        "{%0,%1,%2,%3}, {%4,%5,%6,%7}, {%8,%9}, {%0,%1,%2,%3};"
        : "+f"(d[0]), "+f"(d[1]), "+f"(d[2]), "+f"(d[3])
        : "r"(a[0]), "r"(a[1]), "r"(a[2]), "r"(a[3]), "r"(b0), "r"(b1));
}
__device__ __forceinline__ void ldsm4(uint32_t* r, uint32_t addr) {
    asm volatile("ldmatrix.sync.aligned.m8n8.x4.shared.b16 {%0,%1,%2,%3}, [%4];"
                 : "=r"(r[0]), "=r"(r[1]), "=r"(r[2]), "=r"(r[3]) : "r"(addr));
}

// ---------------------------------------------------------------------------
// W split into mma B-fragment layout (hi/lo bf16) — both layers, one launch.
// ---------------------------------------------------------------------------
__global__ void k_wsplit(const float* __restrict__ W1, const float* __restrict__ W2) {
    int id = blockIdx.x * blockDim.x + threadIdx.x;   // 32768 total
    if (id >= 2 * 16384) return;
    int layer = id >> 14;
    int v     = id & 16383;
    int jr   = v & 7;
    int lane = (v >> 3) & 31;
    int wn   = (v >> 8) & 3;
    int kt   = (v >> 10) & 7;
    int hl   = v >> 13;
    int j = jr >> 1, r = jr & 1;
    int n = (wn * 4 + j) * 8 + (lane >> 2);
    int k = kt * 16 + (lane & 3) * 2 + r * 8;
    const float* W = layer ? W2 : W1;
    float v0 = W[k * F + n];
    float v1 = W[(k + 1) * F + n];
    g_wfrag[layer][hl][kt][wn][lane][jr] = (hl == 0) ? pack_hi(v0, v1) : pack_lo(v0, v1);
}

// ---------------------------------------------------------------------------
// dinv table + per-slot edge weights (after scatter)
// ---------------------------------------------------------------------------
__global__ void k_dinv(int N) {
    int i = blockIdx.x * blockDim.x + threadIdx.x;
    if (i < N) g_dinvf[i] = rsqrtf((float)(g_cursor[i] + 1));
}

__global__ void __launch_bounds__(256)
k_edgew(int N) {
    int node = blockIdx.x * (blockDim.x >> 5) + (threadIdx.x >> 5);
    if (node >= N) return;
    int lane = threadIdx.x & 31;
    int cnt = min(__ldg(&g_cursor[node]), DCAP);
    float dc = __ldg(&g_dinvf[node]);
    for (int s = lane; s < cnt; s += 32) {
        int r = g_eidx[(size_t)node * DCAP + s];
        g_ew[(size_t)node * DCAP + s] = dc * __ldg(&g_dinvf[r]);
    }
}

// ---------------------------------------------------------------------------
// GEMM block body (device function)
// ---------------------------------------------------------------------------
template <bool RELU_A>
__device__ __forceinline__ void gemm_block(
    const float* __restrict__ A, const uint32_t* __restrict__ wfrag,
    float* __restrict__ outP, int M, int bb)
{
    __shared__ __align__(16) __nv_bfloat16 Ah[64][136];
    __shared__ __align__(16) __nv_bfloat16 Al[64][136];

    const int tid  = threadIdx.x;
    const int wid  = tid >> 5;
    const int lane = tid & 31;
    const int wm = wid >> 2;
    const int wn = wid & 3;
    const int block_row = bb * 64;

    #pragma unroll
    for (int it = 0; it < 4; it++) {
        int seg = it * 256 + tid;
        int r  = seg >> 4;
        int sk = (seg & 15) * 8;
        int grow = block_row + r;
        float4 a0 = make_float4(0.f,0.f,0.f,0.f), a1 = a0;
        if (grow < M) {
            a0 = *(const float4*)(A + (size_t)grow * F + sk);
            a1 = *(const float4*)(A + (size_t)grow * F + sk + 4);
        }
        if (RELU_A) {
            a0.x = fmaxf(a0.x,0.f); a0.y = fmaxf(a0.y,0.f); a0.z = fmaxf(a0.z,0.f); a0.w = fmaxf(a0.w,0.f);
            a1.x = fmaxf(a1.x,0.f); a1.y = fmaxf(a1.y,0.f); a1.z = fmaxf(a1.z,0.f); a1.w = fmaxf(a1.w,0.f);
        }
        *(uint4*)&Ah[r][sk] = make_uint4(pack_hi(a0.x,a0.y), pack_hi(a0.z,a0.w),
                                         pack_hi(a1.x,a1.y), pack_hi(a1.z,a1.w));
        *(uint4*)&Al[r][sk] = make_uint4(pack_lo(a0.x,a0.y), pack_lo(a0.z,a0.w),
                                         pack_lo(a1.x,a1.y), pack_lo(a1.z,a1.w));
    }
    __syncthreads();

    float acc[2][4][4];
    #pragma unroll
    for (int mt = 0; mt < 2; mt++)
        #pragma unroll
        for (int j = 0; j < 4; j++)
            #pragma unroll
            for (int q = 0; q < 4; q++) acc[mt][j][q] = 0.f;

    const int mat = lane >> 3, rr = lane & 7;
    const int lrow  = (mat & 1) * 8 + rr;
    const int lkoff = (mat >> 1) * 8;
    const uint32_t aBaseH = smem_u32(&Ah[0][0]);
    const uint32_t aBaseL = smem_u32(&Al[0][0]);

    #pragma unroll
    for (int ks = 0; ks < 8; ks++) {
        uint32_t ah[2][4], al[2][4];
        #pragma unroll
        for (int mt = 0; mt < 2; mt++) {
            uint32_t off = (uint32_t)(((wm * 32 + mt * 16 + lrow) * 136 + ks * 16 + lkoff) * 2);
            ldsm4(ah[mt], aBaseH + off);
            ldsm4(al[mt], aBaseL + off);
        }
        const uint32_t* p_h = wfrag + (((size_t)(0 * 8 + ks) * 4 + wn) * 32 + lane) * 8;
        const uint32_t* p_l = wfrag + (((size_t)(1 * 8 + ks) * 4 + wn) * 32 + lane) * 8;
        uint4 h0 = *(const uint4*)p_h, h1 = *(const uint4*)(p_h + 4);
        uint4 l0 = *(const uint4*)p_l, l1 = *(const uint4*)(p_l + 4);
        uint32_t bh[8] = {h0.x,h0.y,h0.z,h0.w,h1.x,h1.y,h1.z,h1.w};
        uint32_t bl[8] = {l0.x,l0.y,l0.z,l0.w,l1.x,l1.y,l1.z,l1.w};

        #pragma unroll
        for (int mt = 0; mt < 2; mt++)
            #pragma unroll
            for (int j = 0; j < 4; j++) {
                mma_bf16(acc[mt][j], ah[mt], bh[2*j], bh[2*j+1]);
                mma_bf16(acc[mt][j], ah[mt], bl[2*j], bl[2*j+1]);
                mma_bf16(acc[mt][j], al[mt], bh[2*j], bh[2*j+1]);
            }
    }

    const int qrow = lane >> 2;
    const int qcol = (lane & 3) * 2;
    #pragma unroll
    for (int mt = 0; mt < 2; mt++) {
        int r0 = block_row + wm * 32 + mt * 16 + qrow;
        int r1 = r0 + 8;
        #pragma unroll
        for (int j = 0; j < 4; j++) {
            int c = wn * 32 + j * 8 + qcol;
            if (r0 < M) *(float2*)(outP + (size_t)r0 * F + c) = make_float2(acc[mt][j][0], acc[mt][j][1]);
            if (r1 < M) *(float2*)(outP + (size_t)r1 * F + c) = make_float2(acc[mt][j][2], acc[mt][j][3]);
        }
    }
}

// ---------------------------------------------------------------------------
// Mega kernel 1: GEMM layer-1 blocks + edge-scatter blocks (independent work)
// ---------------------------------------------------------------------------
__global__ void __launch_bounds__(256, 2)
k_mega1(const float* __restrict__ A, const uint32_t* __restrict__ wfrag,
        float* __restrict__ outP, const int* __restrict__ ei,
        int M, int E, int gemm_blocks)
{
    if ((int)blockIdx.x < gemm_blocks) {
        gemm_block<false>(A, wfrag, outP, M, blockIdx.x);
        return;
    }
    int e = (blockIdx.x - gemm_blocks) * 256 + threadIdx.x;
    if (e < E) {
        int r = __ldg(ei + e);
        int c = __ldg(ei + E + e);
        int pos = atomicAdd(&g_cursor[c], 1);
        if (pos < DCAP) {
            g_eidx[(size_t)c * DCAP + pos] = r;
        } else {
            int o = atomicAdd(&g_cursor[NMAX], 1);
            if (o < OVFMAX) { g_ovf[2 * o] = r; g_ovf[2 * o + 1] = c; }
        }
    }
}

// Plain GEMM (layer 2)
template <bool RELU_A>
__global__ void __launch_bounds__(256, 2)
k_gemm_mma(const float* __restrict__ A, const uint32_t* __restrict__ wfrag,
           float* __restrict__ outP, int M)
{
    gemm_block<RELU_A>(A, wfrag, outP, M, blockIdx.x);
}

// ---------------------------------------------------------------------------
// Bucket-gather aggregation: one warp per destination node.
// Inner loop: 2 shfls + 1 feature load + FMAs (weights precomputed in g_ew).
// ---------------------------------------------------------------------------
__global__ void __launch_bounds__(256)
k_agg(const float* __restrict__ src, const float* __restrict__ bias,
      float* __restrict__ dst, int N)
{
    int node = blockIdx.x * (blockDim.x >> 5) + (threadIdx.x >> 5);
    if (node >= N) return;
    int lane = threadIdx.x & 31;

    float dc = __ldg(&g_dinvf[node]);
    float s  = dc * dc;

    float4 acc = __ldg((const float4*)(src + (size_t)node * F) + lane);
    float4 bb  = __ldg((const float4*)bias + lane);
    acc.x = fmaf(acc.x, s, bb.x);
    acc.y = fmaf(acc.y, s, bb.y);
    acc.z = fmaf(acc.z, s, bb.z);
    acc.w = fmaf(acc.w, s, bb.w);

    int cr  = __ldg(&g_cursor[node]);
    int cnt = min(cr, DCAP);
    const int*   bucket = g_eidx + (size_t)node * DCAP;
    const float* wts    = g_ew   + (size_t)node * DCAP;

    for (int base = 0; base < cnt; base += 32) {
        int id = 0; float wt = 0.f;
        if (base + lane < cnt) {
            id = __ldg(bucket + base + lane);
            wt = __ldg(wts + base + lane);
        }
        int m = min(cnt - base, 32);
        #pragma unroll 4
        for (int j = 0; j < m; j++) {
            int   r = __shfl_sync(0xffffffff, id, j);
            float w = __shfl_sync(0xffffffff, wt, j);
            float4 v = __ldg((const float4*)(src + (size_t)r * F) + lane);
            acc.x = fmaf(v.x, w, acc.x);
            acc.y = fmaf(v.y, w, acc.y);
            acc.z = fmaf(v.z, w, acc.z);
            acc.w = fmaf(v.w, w, acc.w);
        }
    }

    // Overflow slow path (empty in practice; correctness insurance)
    if (cr > DCAP) {
        int ovfn = min(__ldg(&g_cursor[NMAX]), OVFMAX);
        for (int e = 0; e < ovfn; e++) {
            if (g_ovf[2 * e + 1] == node) {
                int r = g_ovf[2 * e];
                float w = dc * __ldg(&g_dinvf[r]);
                float4 v = __ldg((const float4*)(src + (size_t)r * F) + lane);
                acc.x = fmaf(v.x, w, acc.x);
                acc.y = fmaf(v.y, w, acc.y);
                acc.z = fmaf(v.z, w, acc.z);
                acc.w = fmaf(v.w, w, acc.w);
            }
        }
    }

    *((float4*)(dst + (size_t)node * F) + lane) = acc;
}

// ---------------------------------------------------------------------------
// Launch
// ---------------------------------------------------------------------------
extern "C" void kernel_launch(void* const* d_in, const int* in_sizes, int n_in,
                              void* d_out, int out_size)
{
    const float* x  = (const float*)d_in[0];
    const int*   ei = (const int*)d_in[1];
    const float* W1 = (const float*)d_in[2];
    const float* b1 = (const float*)d_in[3];
    const float* W2 = (const float*)d_in[4];
    const float* b2 = (const float*)d_in[5];
    float*       out = (float*)d_out;

    const int N = in_sizes[0] / F;   // 100000
    const int E = in_sizes[1] / 2;   // 640000

    float* xw;   cudaGetSymbolAddress((void**)&xw,   g_xw);
    float* acc1; cudaGetSymbolAddress((void**)&acc1, g_acc1);
    float* hw;   cudaGetSymbolAddress((void**)&hw,   g_hw);
    int* cursor; cudaGetSymbolAddress((void**)&cursor, g_cursor);
    uint32_t* wfrag; cudaGetSymbolAddress((void**)&wfrag, g_wfrag);
    const size_t WFRAG_LAYER = 2ull * 8 * 4 * 32 * 8;

    const int gemm_blocks = (N + 63) / 64;
    const int scat_blocks = (E + 255) / 256;
    const int agg_blocks  = (N + 7) / 8;

    // Zero bucket cursors + overflow counter
    cudaMemsetAsync(cursor, 0, (NMAX + 1) * sizeof(int));

    // W pre-split (both layers, one launch)
    k_wsplit<<<128, 256>>>(W1, W2);

    // GEMM1 + edge scatter fused
    k_mega1<<<gemm_blocks + scat_blocks, 256>>>(x, wfrag, xw, ei, N, E, gemm_blocks);

    // dinv table + per-slot edge weights
    k_dinv <<<(N + 255) / 256, 256>>>(N);
    k_edgew<<<agg_blocks, 256>>>(N);

    // Layer 1 aggregation
    k_agg<<<agg_blocks, 256>>>(xw, b1, acc1, N);

    // Layer 2
    k_gemm_mma<true><<<gemm_blocks, 256>>>(acc1, wfrag + WFRAG_LAYER, hw, N);
    k_agg<<<agg_blocks, 256>>>(hw, b2, out, N);
}

// round 9
// speedup vs baseline: 1.4116x; 1.1890x over previous
#include <cuda_runtime.h>
#include <cuda_bf16.h>
#include <cuda_fp16.h>
#include <stdint.h>

#define NMAX   100000
#define F      128
#define DCAP   64          // bucket capacity per node (P(deg>64) ~ 0 for lambda=6.4)
#define OVFMAX 8192        // overflow-edge safety list

// Scratch (allocation-free rule: __device__ globals)
__device__ __half g_xw_h[NMAX * F];       // layer-1 product, fp16 (gather source)
__device__ float  g_acc1[NMAX * F];       // layer-1 aggregated activation, fp32
__device__ __half g_hw_h[NMAX * F];       // layer-2 product, fp16 (gather source)
__device__ int    g_cursor[NMAX + 1];     // [N] = overflow counter
__device__ int    g_eidx[NMAX * DCAP];    // per-dst neighbor buckets
__device__ int    g_ovf [2 * OVFMAX];     // (r,c) pairs that overflowed
// W in mma B-fragment layout: [layer][hl][ktile(8)][warp_n(4)][lane(32)][8 u32]
__device__ uint32_t g_wfrag[2][2][8][4][32][8];

// ---------------------------------------------------------------------------
// Helpers
// ---------------------------------------------------------------------------
__device__ __forceinline__ uint32_t smem_u32(const void* p) {
    uint32_t a;
    asm("{ .reg .u64 t; cvta.to.shared.u64 t, %1; cvt.u32.u64 %0, t; }" : "=r"(a) : "l"(p));
    return a;
}
__device__ __forceinline__ uint32_t pack_hi(float a, float b) {
    __nv_bfloat16 x = __float2bfloat16_rn(a), y = __float2bfloat16_rn(b);
    return (uint32_t)*(unsigned short*)&x | ((uint32_t)*(unsigned short*)&y << 16);
}
__device__ __forceinline__ uint32_t pack_lo(float a, float b) {
    __nv_bfloat16 x = __float2bfloat16_rn(a), y = __float2bfloat16_rn(b);
    float ra = a - __bfloat162float(x), rb = b - __bfloat162float(y);
    __nv_bfloat16 lx = __float2bfloat16_rn(ra), ly = __float2bfloat16_rn(rb);
    return (uint32_t)*(unsigned short*)&lx | ((uint32_t)*(unsigned short*)&ly << 16);
}
__device__ __forceinline__ void mma_bf16(float* d, const uint32_t* a, uint32_t b0, uint32_t b1) {
    asm volatile(
        "mma.sync.aligned.m16n8k16.row.col.f32.bf16.bf16.f32 "
        "{%0,%1,%2,%3}, {%4,%5,%6,%7}, {%8,%9}, {%0,%1,%2,%3};"
        : "+f"(d[0]), "+f"(d[1]), "+f"(d[2]), "+f"(d[3])
        : "r"(a[0]), "r"(a[1]), "r"(a[2]), "r"(a[3]), "r"(b0), "r"(b1));
}
__device__ __forceinline__ void ldsm4(uint32_t* r, uint32_t addr) {
    asm volatile("ldmatrix.sync.aligned.m8n8.x4.shared.b16 {%0,%1,%2,%3}, [%4];"
                 : "=r"(r[0]), "=r"(r[1]), "=r"(r[2]), "=r"(r[3]) : "r"(addr));
}

// ---------------------------------------------------------------------------
// W split into mma B-fragment layout (hi/lo bf16) — both layers, one launch.
// ---------------------------------------------------------------------------
__global__ void k_wsplit(const float* __restrict__ W1, const float* __restrict__ W2) {
    int id = blockIdx.x * blockDim.x + threadIdx.x;   // 32768 total
    if (id >= 2 * 16384) return;
    int layer = id >> 14;
    int v     = id & 16383;
    int jr   = v & 7;
    int lane = (v >> 3) & 31;
    int wn   = (v >> 8) & 3;
    int kt   = (v >> 10) & 7;
    int hl   = v >> 13;
    int j = jr >> 1, r = jr & 1;
    int n = (wn * 4 + j) * 8 + (lane >> 2);
    int k = kt * 16 + (lane & 3) * 2 + r * 8;
    const float* W = layer ? W2 : W1;
    float v0 = W[k * F + n];
    float v1 = W[(k + 1) * F + n];
    g_wfrag[layer][hl][kt][wn][lane][jr] = (hl == 0) ? pack_hi(v0, v1) : pack_lo(v0, v1);
}

// ---------------------------------------------------------------------------
// GEMM block body: A fp32 in, product out as fp16 (gather source format)
// ---------------------------------------------------------------------------
template <bool RELU_A>
__device__ __forceinline__ void gemm_block(
    const float* __restrict__ A, const uint32_t* __restrict__ wfrag,
    __half* __restrict__ outH, int M, int bb)
{
    __shared__ __align__(16) __nv_bfloat16 Ah[64][136];
    __shared__ __align__(16) __nv_bfloat16 Al[64][136];

    const int tid  = threadIdx.x;
    const int wid  = tid >> 5;
    const int lane = tid & 31;
    const int wm = wid >> 2;
    const int wn = wid & 3;
    const int block_row = bb * 64;

    #pragma unroll
    for (int it = 0; it < 4; it++) {
        int seg = it * 256 + tid;
        int r  = seg >> 4;
        int sk = (seg & 15) * 8;
        int grow = block_row + r;
        float4 a0 = make_float4(0.f,0.f,0.f,0.f), a1 = a0;
        if (grow < M) {
            a0 = *(const float4*)(A + (size_t)grow * F + sk);
            a1 = *(const float4*)(A + (size_t)grow * F + sk + 4);
        }
        if (RELU_A) {
            a0.x = fmaxf(a0.x,0.f); a0.y = fmaxf(a0.y,0.f); a0.z = fmaxf(a0.z,0.f); a0.w = fmaxf(a0.w,0.f);
            a1.x = fmaxf(a1.x,0.f); a1.y = fmaxf(a1.y,0.f); a1.z = fmaxf(a1.z,0.f); a1.w = fmaxf(a1.w,0.f);
        }
        *(uint4*)&Ah[r][sk] = make_uint4(pack_hi(a0.x,a0.y), pack_hi(a0.z,a0.w),
                                         pack_hi(a1.x,a1.y), pack_hi(a1.z,a1.w));
        *(uint4*)&Al[r][sk] = make_uint4(pack_lo(a0.x,a0.y), pack_lo(a0.z,a0.w),
                                         pack_lo(a1.x,a1.y), pack_lo(a1.z,a1.w));
    }
    __syncthreads();

    float acc[2][4][4];
    #pragma unroll
    for (int mt = 0; mt < 2; mt++)
        #pragma unroll
        for (int j = 0; j < 4; j++)
            #pragma unroll
            for (int q = 0; q < 4; q++) acc[mt][j][q] = 0.f;

    const int mat = lane >> 3, rr = lane & 7;
    const int lrow  = (mat & 1) * 8 + rr;
    const int lkoff = (mat >> 1) * 8;
    const uint32_t aBaseH = smem_u32(&Ah[0][0]);
    const uint32_t aBaseL = smem_u32(&Al[0][0]);

    #pragma unroll
    for (int ks = 0; ks < 8; ks++) {
        uint32_t ah[2][4], al[2][4];
        #pragma unroll
        for (int mt = 0; mt < 2; mt++) {
            uint32_t off = (uint32_t)(((wm * 32 + mt * 16 + lrow) * 136 + ks * 16 + lkoff) * 2);
            ldsm4(ah[mt], aBaseH + off);
            ldsm4(al[mt], aBaseL + off);
        }
        const uint32_t* p_h = wfrag + (((size_t)(0 * 8 + ks) * 4 + wn) * 32 + lane) * 8;
        const uint32_t* p_l = wfrag + (((size_t)(1 * 8 + ks) * 4 + wn) * 32 + lane) * 8;
        uint4 h0 = *(const uint4*)p_h, h1 = *(const uint4*)(p_h + 4);
        uint4 l0 = *(const uint4*)p_l, l1 = *(const uint4*)(p_l + 4);
        uint32_t bh[8] = {h0.x,h0.y,h0.z,h0.w,h1.x,h1.y,h1.z,h1.w};
        uint32_t bl[8] = {l0.x,l0.y,l0.z,l0.w,l1.x,l1.y,l1.z,l1.w};

        #pragma unroll
        for (int mt = 0; mt < 2; mt++)
            #pragma unroll
            for (int j = 0; j < 4; j++) {
                mma_bf16(acc[mt][j], ah[mt], bh[2*j], bh[2*j+1]);
                mma_bf16(acc[mt][j], ah[mt], bl[2*j], bl[2*j+1]);
                mma_bf16(acc[mt][j], al[mt], bh[2*j], bh[2*j+1]);
            }
    }

    const int qrow = lane >> 2;
    const int qcol = (lane & 3) * 2;
    #pragma unroll
    for (int mt = 0; mt < 2; mt++) {
        int r0 = block_row + wm * 32 + mt * 16 + qrow;
        int r1 = r0 + 8;
        #pragma unroll
        for (int j = 0; j < 4; j++) {
            int c = wn * 32 + j * 8 + qcol;
            if (r0 < M)
                *(__half2*)(outH + (size_t)r0 * F + c) =
                    __float22half2_rn(make_float2(acc[mt][j][0], acc[mt][j][1]));
            if (r1 < M)
                *(__half2*)(outH + (size_t)r1 * F + c) =
                    __float22half2_rn(make_float2(acc[mt][j][2], acc[mt][j][3]));
        }
    }
}

// ---------------------------------------------------------------------------
// Mega kernel 1: GEMM layer-1 blocks + edge-scatter blocks (independent work)
// ---------------------------------------------------------------------------
__global__ void __launch_bounds__(256, 2)
k_mega1(const float* __restrict__ A, const uint32_t* __restrict__ wfrag,
        __half* __restrict__ outH, const int* __restrict__ ei,
        int M, int E, int gemm_blocks)
{
    if ((int)blockIdx.x < gemm_blocks) {
        gemm_block<false>(A, wfrag, outH, M, blockIdx.x);
        return;
    }
    int e = (blockIdx.x - gemm_blocks) * 256 + threadIdx.x;
    if (e < E) {
        int r = __ldg(ei + e);
        int c = __ldg(ei + E + e);
        int pos = atomicAdd(&g_cursor[c], 1);
        if (pos < DCAP) {
            g_eidx[(size_t)c * DCAP + pos] = r;
        } else {
            int o = atomicAdd(&g_cursor[NMAX], 1);
            if (o < OVFMAX) { g_ovf[2 * o] = r; g_ovf[2 * o + 1] = c; }
        }
    }
}

// Plain GEMM (layer 2): acc1 fp32 -> hw fp16
template <bool RELU_A>
__global__ void __launch_bounds__(256, 2)
k_gemm_mma(const float* __restrict__ A, const uint32_t* __restrict__ wfrag,
           __half* __restrict__ outH, int M)
{
    gemm_block<RELU_A>(A, wfrag, outH, M, blockIdx.x);
}

// ---------------------------------------------------------------------------
// Bucket-gather aggregation: one warp per destination node, fp16 source.
//   dst[c] = bias + dinv[c]^2*src[c] + sum_{r in in(c)} dinv[c]*dinv[r]*src[r]
// Each lane owns 4 columns: loads uint2 = 2 x half2, fp32 accumulate.
// ---------------------------------------------------------------------------
__device__ __forceinline__ void acc_half4(float4& acc, const __half* row, int lane, float w) {
    uint2 u = __ldg((const uint2*)row + lane);
    float2 lo = __half22float2(*(const __half2*)&u.x);
    float2 hi = __half22float2(*(const __half2*)&u.y);
    acc.x = fmaf(lo.x, w, acc.x);
    acc.y = fmaf(lo.y, w, acc.y);
    acc.z = fmaf(hi.x, w, acc.z);
    acc.w = fmaf(hi.y, w, acc.w);
}

__global__ void __launch_bounds__(256)
k_agg(const __half* __restrict__ src, const float* __restrict__ bias,
      float* __restrict__ dst, int N)
{
    int node = blockIdx.x * (blockDim.x >> 5) + (threadIdx.x >> 5);
    if (node >= N) return;
    int lane = threadIdx.x & 31;

    int cr = __ldg(&g_cursor[node]);
    float dc = rsqrtf((float)(cr + 1));
    float s  = dc * dc;

    float4 acc = __ldg((const float4*)bias + lane);
    acc_half4(acc, src + (size_t)node * F, lane, s);

    int cnt = min(cr, DCAP);
    const int* bucket = g_eidx + (size_t)node * DCAP;

    for (int base = 0; base < cnt; base += 32) {
        int id = 0;
        if (base + lane < cnt) id = __ldg(bucket + base + lane);
        int m = min(cnt - base, 32);
        #pragma unroll 4
        for (int j = 0; j < m; j++) {
            int r = __shfl_sync(0xffffffff, id, j);
            float dr = rsqrtf((float)(__ldg(&g_cursor[r]) + 1));
            acc_half4(acc, src + (size_t)r * F, lane, dc * dr);
        }
    }

    // Overflow slow path (empty in practice; correctness insurance)
    if (cr > DCAP) {
        int ovfn = min(__ldg(&g_cursor[NMAX]), OVFMAX);
        for (int e = 0; e < ovfn; e++) {
            if (g_ovf[2 * e + 1] == node) {
                int r = g_ovf[2 * e];
                float dr = rsqrtf((float)(__ldg(&g_cursor[r]) + 1));
                acc_half4(acc, src + (size_t)r * F, lane, dc * dr);
            }
        }
    }

    *((float4*)(dst + (size_t)node * F) + lane) = acc;
}

// ---------------------------------------------------------------------------
// Launch
// ---------------------------------------------------------------------------
extern "C" void kernel_launch(void* const* d_in, const int* in_sizes, int n_in,
                              void* d_out, int out_size)
{
    const float* x  = (const float*)d_in[0];
    const int*   ei = (const int*)d_in[1];
    const float* W1 = (const float*)d_in[2];
    const float* b1 = (const float*)d_in[3];
    const float* W2 = (const float*)d_in[4];
    const float* b2 = (const float*)d_in[5];
    float*       out = (float*)d_out;

    const int N = in_sizes[0] / F;   // 100000
    const int E = in_sizes[1] / 2;   // 640000

    __half* xwh; cudaGetSymbolAddress((void**)&xwh, g_xw_h);
    float*  acc1; cudaGetSymbolAddress((void**)&acc1, g_acc1);
    __half* hwh; cudaGetSymbolAddress((void**)&hwh, g_hw_h);
    int* cursor; cudaGetSymbolAddress((void**)&cursor, g_cursor);
    uint32_t* wfrag; cudaGetSymbolAddress((void**)&wfrag, g_wfrag);
    const size_t WFRAG_LAYER = 2ull * 8 * 4 * 32 * 8;

    const int gemm_blocks = (N + 63) / 64;
    const int scat_blocks = (E + 255) / 256;
    const int agg_blocks  = (N + 7) / 8;

    // Zero bucket cursors + overflow counter
    cudaMemsetAsync(cursor, 0, (NMAX + 1) * sizeof(int));

    // W pre-split (both layers, one launch)
    k_wsplit<<<128, 256>>>(W1, W2);

    // GEMM1 + edge scatter fused: xw_h = (x @ W1) as fp16
    k_mega1<<<gemm_blocks + scat_blocks, 256>>>(x, wfrag, xwh, ei, N, E, gemm_blocks);

    // Layer 1 aggregation: acc1 = Â·xw_h + b1  (fp32)
    k_agg<<<agg_blocks, 256>>>(xwh, b1, acc1, N);

    // Layer 2 GEMM: hw_h = (relu(acc1) @ W2) as fp16
    k_gemm_mma<true><<<gemm_blocks, 256>>>(acc1, wfrag + WFRAG_LAYER, hwh, N);

    // Final aggregation: out = Â·hw_h + b2  (fp32)
    k_agg<<<agg_blocks, 256>>>(hwh, b2, out, N);
}

// round 10
// speedup vs baseline: 1.4566x; 1.0319x over previous
#include <cuda_runtime.h>
#include <cuda_bf16.h>
#include <cuda_fp16.h>
#include <stdint.h>

#define NMAX   100000
#define F      128
#define DCAP   64          // bucket capacity per node (P(deg>64) ~ 0 for lambda=6.4)
#define OVFMAX 8192        // overflow-edge safety list

#define BM     128         // CTA tile rows
#define SMEM_BYTES (2 * BM * 136 * 2)   // Ah + Al, bf16, padded stride 136

// Scratch (allocation-free rule: __device__ globals)
__device__ __half g_xw_h[NMAX * F];       // layer-1 product, fp16 (gather source)
__device__ float  g_acc1[NMAX * F];       // layer-1 aggregated activation, fp32
__device__ __half g_hw_h[NMAX * F];       // layer-2 product, fp16 (gather source)
__device__ int    g_cursor[NMAX + 1];     // [N] = overflow counter
__device__ int    g_eidx[NMAX * DCAP];    // per-dst neighbor buckets
__device__ int    g_ovf [2 * OVFMAX];     // (r,c) pairs that overflowed
// W in mma B-fragment layout: [layer][hl][ktile(8)][warp_n(4)][lane(32)][8 u32]
__device__ uint32_t g_wfrag[2][2][8][4][32][8];

// ---------------------------------------------------------------------------
// Helpers
// ---------------------------------------------------------------------------
__device__ __forceinline__ uint32_t smem_u32(const void* p) {
    uint32_t a;
    asm("{ .reg .u64 t; cvta.to.shared.u64 t, %1; cvt.u32.u64 %0, t; }" : "=r"(a) : "l"(p));
    return a;
}
__device__ __forceinline__ uint32_t pack_hi(float a, float b) {
    __nv_bfloat16 x = __float2bfloat16_rn(a), y = __float2bfloat16_rn(b);
    return (uint32_t)*(unsigned short*)&x | ((uint32_t)*(unsigned short*)&y << 16);
}
__device__ __forceinline__ uint32_t pack_lo(float a, float b) {
    __nv_bfloat16 x = __float2bfloat16_rn(a), y = __float2bfloat16_rn(b);
    float ra = a - __bfloat162float(x), rb = b - __bfloat162float(y);
    __nv_bfloat16 lx = __float2bfloat16_rn(ra), ly = __float2bfloat16_rn(rb);
    return (uint32_t)*(unsigned short*)&lx | ((uint32_t)*(unsigned short*)&ly << 16);
}
__device__ __forceinline__ void mma_bf16(float* d, const uint32_t* a, uint32_t b0, uint32_t b1) {
    asm volatile(
        "mma.sync.aligned.m16n8k16.row.col.f32.bf16.bf16.f32 "
        "{%0,%1,%2,%3}, {%4,%5,%6,%7}, {%8,%9}, {%0,%1,%2,%3};"
        : "+f"(d[0]), "+f"(d[1]), "+f"(d[2]), "+f"(d[3])
        : "r"(a[0]), "r"(a[1]), "r"(a[2]), "r"(a[3]), "r"(b0), "r"(b1));
}
__device__ __forceinline__ void ldsm4(uint32_t* r, uint32_t addr) {
    asm volatile("ldmatrix.sync.aligned.m8n8.x4.shared.b16 {%0,%1,%2,%3}, [%4];"
                 : "=r"(r[0]), "=r"(r[1]), "=r"(r[2]), "=r"(r[3]) : "r"(addr));
}

// ---------------------------------------------------------------------------
// W split into mma B-fragment layout (hi/lo bf16) — both layers, one launch.
// ---------------------------------------------------------------------------
__global__ void k_wsplit(const float* __restrict__ W1, const float* __restrict__ W2) {
    int id = blockIdx.x * blockDim.x + threadIdx.x;   // 32768 total
    if (id >= 2 * 16384) return;
    int layer = id >> 14;
    int v     = id & 16383;
    int jr   = v & 7;
    int lane = (v >> 3) & 31;
    int wn   = (v >> 8) & 3;
    int kt   = (v >> 10) & 7;
    int hl   = v >> 13;
    int j = jr >> 1, r = jr & 1;
    int n = (wn * 4 + j) * 8 + (lane >> 2);
    int k = kt * 16 + (lane & 3) * 2 + r * 8;
    const float* W = layer ? W2 : W1;
    float v0 = W[k * F + n];
    float v1 = W[(k + 1) * F + n];
    g_wfrag[layer][hl][kt][wn][lane][jr] = (hl == 0) ? pack_hi(v0, v1) : pack_lo(v0, v1);
}

// ---------------------------------------------------------------------------
// GEMM block body: 128-row CTA tile, warp tile 64x32 (2x4 warp grid).
// A fp32 in (optional ReLU), product out as fp16.
// ---------------------------------------------------------------------------
template <bool RELU_A>
__device__ __forceinline__ void gemm_block(
    const float* __restrict__ A, const uint32_t* __restrict__ wfrag,
    __half* __restrict__ outH, int M, int bb, __nv_bfloat16* smem)
{
    __nv_bfloat16 (*Ah)[136] = (__nv_bfloat16(*)[136])smem;
    __nv_bfloat16 (*Al)[136] = (__nv_bfloat16(*)[136])(smem + BM * 136);

    const int tid  = threadIdx.x;
    const int wid  = tid >> 5;
    const int lane = tid & 31;
    const int wm = wid >> 2;     // 0..1 -> 64-row half
    const int wn = wid & 3;      // 0..3 -> 32-col slab
    const int block_row = bb * BM;

    // Fill A hi/lo tiles: 128 rows x 16 segs = 2048 segs / 256 thr = 8 iters
    #pragma unroll
    for (int it = 0; it < 8; it++) {
        int seg = it * 256 + tid;
        int r  = seg >> 4;
        int sk = (seg & 15) * 8;
        int grow = block_row + r;
        float4 a0 = make_float4(0.f,0.f,0.f,0.f), a1 = a0;
        if (grow < M) {
            a0 = *(const float4*)(A + (size_t)grow * F + sk);
            a1 = *(const float4*)(A + (size_t)grow * F + sk + 4);
        }
        if (RELU_A) {
            a0.x = fmaxf(a0.x,0.f); a0.y = fmaxf(a0.y,0.f); a0.z = fmaxf(a0.z,0.f); a0.w = fmaxf(a0.w,0.f);
            a1.x = fmaxf(a1.x,0.f); a1.y = fmaxf(a1.y,0.f); a1.z = fmaxf(a1.z,0.f); a1.w = fmaxf(a1.w,0.f);
        }
        *(uint4*)&Ah[r][sk] = make_uint4(pack_hi(a0.x,a0.y), pack_hi(a0.z,a0.w),
                                         pack_hi(a1.x,a1.y), pack_hi(a1.z,a1.w));
        *(uint4*)&Al[r][sk] = make_uint4(pack_lo(a0.x,a0.y), pack_lo(a0.z,a0.w),
                                         pack_lo(a1.x,a1.y), pack_lo(a1.z,a1.w));
    }
    __syncthreads();

    float acc[4][4][4];
    #pragma unroll
    for (int mt = 0; mt < 4; mt++)
        #pragma unroll
        for (int j = 0; j < 4; j++)
            #pragma unroll
            for (int q = 0; q < 4; q++) acc[mt][j][q] = 0.f;

    const int mat = lane >> 3, rr = lane & 7;
    const int lrow  = (mat & 1) * 8 + rr;
    const int lkoff = (mat >> 1) * 8;
    const uint32_t aBaseH = smem_u32(&Ah[0][0]);
    const uint32_t aBaseL = smem_u32(&Al[0][0]);

    #pragma unroll
    for (int ks = 0; ks < 8; ks++) {
        // B fragments for this warp's 32-col slab (hi + lo)
        const uint32_t* p_h = wfrag + (((size_t)(0 * 8 + ks) * 4 + wn) * 32 + lane) * 8;
        const uint32_t* p_l = wfrag + (((size_t)(1 * 8 + ks) * 4 + wn) * 32 + lane) * 8;
        uint4 h0 = *(const uint4*)p_h, h1 = *(const uint4*)(p_h + 4);
        uint4 l0 = *(const uint4*)p_l, l1 = *(const uint4*)(p_l + 4);
        uint32_t bh[8] = {h0.x,h0.y,h0.z,h0.w,h1.x,h1.y,h1.z,h1.w};
        uint32_t bl[8] = {l0.x,l0.y,l0.z,l0.w,l1.x,l1.y,l1.z,l1.w};

        #pragma unroll
        for (int mt = 0; mt < 4; mt++) {
            uint32_t ah[4], al[4];
            uint32_t off = (uint32_t)(((wm * 64 + mt * 16 + lrow) * 136 + ks * 16 + lkoff) * 2);
            ldsm4(ah, aBaseH + off);
            ldsm4(al, aBaseL + off);
            #pragma unroll
            for (int j = 0; j < 4; j++) {
                mma_bf16(acc[mt][j], ah, bh[2*j], bh[2*j+1]);
                mma_bf16(acc[mt][j], ah, bl[2*j], bl[2*j+1]);
                mma_bf16(acc[mt][j], al, bh[2*j], bh[2*j+1]);
            }
        }
    }

    const int qrow = lane >> 2;
    const int qcol = (lane & 3) * 2;
    #pragma unroll
    for (int mt = 0; mt < 4; mt++) {
        int r0 = block_row + wm * 64 + mt * 16 + qrow;
        int r1 = r0 + 8;
        #pragma unroll
        for (int j = 0; j < 4; j++) {
            int c = wn * 32 + j * 8 + qcol;
            if (r0 < M)
                *(__half2*)(outH + (size_t)r0 * F + c) =
                    __float22half2_rn(make_float2(acc[mt][j][0], acc[mt][j][1]));
            if (r1 < M)
                *(__half2*)(outH + (size_t)r1 * F + c) =
                    __float22half2_rn(make_float2(acc[mt][j][2], acc[mt][j][3]));
        }
    }
}

// ---------------------------------------------------------------------------
// Mega kernel 1: GEMM layer-1 blocks + edge-scatter blocks (independent work)
// ---------------------------------------------------------------------------
__global__ void __launch_bounds__(256, 2)
k_mega1(const float* __restrict__ A, const uint32_t* __restrict__ wfrag,
        __half* __restrict__ outH, const int* __restrict__ ei,
        int M, int E, int gemm_blocks)
{
    extern __shared__ __nv_bfloat16 smem_dyn[];
    if ((int)blockIdx.x < gemm_blocks) {
        gemm_block<false>(A, wfrag, outH, M, blockIdx.x, smem_dyn);
        return;
    }
    int e = (blockIdx.x - gemm_blocks) * 256 + threadIdx.x;
    if (e < E) {
        int r = __ldg(ei + e);
        int c = __ldg(ei + E + e);
        int pos = atomicAdd(&g_cursor[c], 1);
        if (pos < DCAP) {
            g_eidx[(size_t)c * DCAP + pos] = r;
        } else {
            int o = atomicAdd(&g_cursor[NMAX], 1);
            if (o < OVFMAX) { g_ovf[2 * o] = r; g_ovf[2 * o + 1] = c; }
        }
    }
}

// Plain GEMM (layer 2): acc1 fp32 -> hw fp16
template <bool RELU_A>
__global__ void __launch_bounds__(256, 2)
k_gemm_mma(const float* __restrict__ A, const uint32_t* __restrict__ wfrag,
           __half* __restrict__ outH, int M)
{
    extern __shared__ __nv_bfloat16 smem_dyn[];
    gemm_block<RELU_A>(A, wfrag, outH, M, blockIdx.x, smem_dyn);
}

// ---------------------------------------------------------------------------
// Bucket-gather aggregation: one warp per destination node, fp16 source.
// ---------------------------------------------------------------------------
__device__ __forceinline__ void acc_half4(float4& acc, const __half* row, int lane, float w) {
    uint2 u = __ldg((const uint2*)row + lane);
    float2 lo = __half22float2(*(const __half2*)&u.x);
    float2 hi = __half22float2(*(const __half2*)&u.y);
    acc.x = fmaf(lo.x, w, acc.x);
    acc.y = fmaf(lo.y, w, acc.y);
    acc.z = fmaf(hi.x, w, acc.z);
    acc.w = fmaf(hi.y, w, acc.w);
}

__global__ void __launch_bounds__(256)
k_agg(const __half* __restrict__ src, const float* __restrict__ bias,
      float* __restrict__ dst, int N)
{
    int node = blockIdx.x * (blockDim.x >> 5) + (threadIdx.x >> 5);
    if (node >= N) return;
    int lane = threadIdx.x & 31;

    int cr = __ldg(&g_cursor[node]);
    float dc = rsqrtf((float)(cr + 1));
    float s  = dc * dc;

    float4 acc = __ldg((const float4*)bias + lane);
    acc_half4(acc, src + (size_t)node * F, lane, s);

    int cnt = min(cr, DCAP);
    const int* bucket = g_eidx + (size_t)node * DCAP;

    for (int base = 0; base < cnt; base += 32) {
        int id = 0;
        if (base + lane < cnt) id = __ldg(bucket + base + lane);
        int m = min(cnt - base, 32);
        #pragma unroll 4
        for (int j = 0; j < m; j++) {
            int r = __shfl_sync(0xffffffff, id, j);
            float dr = rsqrtf((float)(__ldg(&g_cursor[r]) + 1));
            acc_half4(acc, src + (size_t)r * F, lane, dc * dr);
        }
    }

    // Overflow slow path (empty in practice; correctness insurance)
    if (cr > DCAP) {
        int ovfn = min(__ldg(&g_cursor[NMAX]), OVFMAX);
        for (int e = 0; e < ovfn; e++) {
            if (g_ovf[2 * e + 1] == node) {
                int r = g_ovf[2 * e];
                float dr = rsqrtf((float)(__ldg(&g_cursor[r]) + 1));
                acc_half4(acc, src + (size_t)r * F, lane, dc * dr);
            }
        }
    }

    *((float4*)(dst + (size_t)node * F) + lane) = acc;
}

// ---------------------------------------------------------------------------
// Launch
// ---------------------------------------------------------------------------
extern "C" void kernel_launch(void* const* d_in, const int* in_sizes, int n_in,
                              void* d_out, int out_size)
{
    const float* x  = (const float*)d_in[0];
    const int*   ei = (const int*)d_in[1];
    const float* W1 = (const float*)d_in[2];
    const float* b1 = (const float*)d_in[3];
    const float* W2 = (const float*)d_in[4];
    const float* b2 = (const float*)d_in[5];
    float*       out = (float*)d_out;

    const int N = in_sizes[0] / F;   // 100000
    const int E = in_sizes[1] / 2;   // 640000

    __half* xwh; cudaGetSymbolAddress((void**)&xwh, g_xw_h);
    float*  acc1; cudaGetSymbolAddress((void**)&acc1, g_acc1);
    __half* hwh; cudaGetSymbolAddress((void**)&hwh, g_hw_h);
    int* cursor; cudaGetSymbolAddress((void**)&cursor, g_cursor);
    uint32_t* wfrag; cudaGetSymbolAddress((void**)&wfrag, g_wfrag);
    const size_t WFRAG_LAYER = 2ull * 8 * 4 * 32 * 8;

    cudaFuncSetAttribute(k_mega1, cudaFuncAttributeMaxDynamicSharedMemorySize, SMEM_BYTES);
    cudaFuncSetAttribute(k_gemm_mma<true>, cudaFuncAttributeMaxDynamicSharedMemorySize, SMEM_BYTES);

    const int gemm_blocks = (N + BM - 1) / BM;
    const int scat_blocks = (E + 255) / 256;
    const int agg_blocks  = (N + 7) / 8;

    // Zero bucket cursors + overflow counter
    cudaMemsetAsync(cursor, 0, (NMAX + 1) * sizeof(int));

    // W pre-split (both layers, one launch)
    k_wsplit<<<128, 256>>>(W1, W2);

    // GEMM1 + edge scatter fused: xw_h = (x @ W1) as fp16
    k_mega1<<<gemm_blocks + scat_blocks, 256, SMEM_BYTES>>>(x, wfrag, xwh, ei, N, E, gemm_blocks);

    // Layer 1 aggregation: acc1 = Â·xw_h + b1  (fp32)
    k_agg<<<agg_blocks, 256>>>(xwh, b1, acc1, N);

    // Layer 2 GEMM: hw_h = (relu(acc1) @ W2) as fp16
    k_gemm_mma<true><<<gemm_blocks, 256, SMEM_BYTES>>>(acc1, wfrag + WFRAG_LAYER, hwh, N);

    // Final aggregation: out = Â·hw_h + b2  (fp32)
    k_agg<<<agg_blocks, 256>>>(hwh, b2, out, N);
}